// round 8
// baseline (speedup 1.0000x reference)
#include <cuda_runtime.h>
#include <math.h>
#include <stdint.h>

#define BATCH 2
#define SEQ 2048
#define HIDDEN 2048
#define NH 16
#define KVH 4
#define HD 128
#define MTOT (BATCH*SEQ)
#define QKVW 3072                 // fused qkv row width
#define KOFF 2048                 // k col offset in qkv
#define VOFF 2560                 // v col offset in qkv

// scratch (no allocation allowed -> device globals)
__device__ float g_qkv[MTOT*QKVW];            // [t][q(2048) | k(512) | v(512)]
__device__ float g_ctx[MTOT*HIDDEN];
__device__ float g_hs[MTOT*HIDDEN];           // tf32-rounded hidden states
__device__ float g_wqkv[QKVW*HIDDEN];         // rows: Wq(2048) | Wk(512) | Wv(512)
__device__ float g_wo[HIDDEN*HIDDEN];

// ===========================================================================
// helpers
// ===========================================================================
__device__ __forceinline__ uint32_t smem_u32(const void* p) {
    uint32_t a;
    asm("{ .reg .u64 t; cvta.to.shared.u64 t, %1; cvt.u32.u64 %0, t; }"
        : "=r"(a) : "l"(p));
    return a;
}
__device__ __forceinline__ void cp_async16(uint32_t saddr, const void* gaddr) {
    asm volatile("cp.async.cg.shared.global [%0], [%1], 16;"
                 :: "r"(saddr), "l"(gaddr));
}
__device__ __forceinline__ void cp_commit() {
    asm volatile("cp.async.commit_group;" ::: "memory");
}
__device__ __forceinline__ void cp_wait1() {
    asm volatile("cp.async.wait_group 1;" ::: "memory");
}
__device__ __forceinline__ float tf32_round(float x) {
    uint32_t u;
    asm("cvt.rna.tf32.f32 %0, %1;" : "=r"(u) : "f"(x));
    return __uint_as_float(u);
}
__device__ __forceinline__ void mma_tf32(float* d, const uint32_t* a, const uint32_t* b) {
    asm volatile(
        "mma.sync.aligned.m16n8k8.row.col.f32.tf32.tf32.f32 "
        "{%0,%1,%2,%3}, {%4,%5,%6,%7}, {%8,%9}, {%0,%1,%2,%3};"
        : "+f"(d[0]), "+f"(d[1]), "+f"(d[2]), "+f"(d[3])
        : "r"(a[0]), "r"(a[1]), "r"(a[2]), "r"(a[3]), "r"(b[0]), "r"(b[1]));
}

// ===========================================================================
// fused tf32 rounding pass: hs -> g_hs, [Wq|Wk|Wv] -> g_wqkv, Wo -> g_wo
// ===========================================================================
#define N4_HS  (MTOT*HIDDEN/4)
#define N4_WQ  (HIDDEN*HIDDEN/4)
#define N4_WKV (KVH*HD*HIDDEN/4)
#define N4_TOT (N4_HS + 2*N4_WQ + 2*N4_WKV)

__global__ void round5_kernel(
    const float* __restrict__ hs, const float* __restrict__ wq,
    const float* __restrict__ wk, const float* __restrict__ wv,
    const float* __restrict__ wo,
    float* __restrict__ dhs, float* __restrict__ dwqkv,
    float* __restrict__ dwo)
{
    int i = blockIdx.x * 256 + threadIdx.x;
    if (i >= N4_TOT) return;
    const float* src; float* dst; int j = i;
    if (j < N4_HS)                  { src = hs; dst = dhs; }
    else if ((j -= N4_HS) < N4_WQ)  { src = wq; dst = dwqkv; }
    else if ((j -= N4_WQ) < N4_WKV) { src = wk; dst = dwqkv + (size_t)KOFF*HIDDEN; }
    else if ((j -= N4_WKV) < N4_WKV){ src = wv; dst = dwqkv + (size_t)VOFF*HIDDEN; }
    else { j -= N4_WKV; src = wo; dst = dwo; }
    float4 v = ((const float4*)src)[j];
    v.x = tf32_round(v.x); v.y = tf32_round(v.y);
    v.z = tf32_round(v.z); v.w = tf32_round(v.w);
    ((float4*)dst)[j] = v;
}

// ===========================================================================
// tf32 mma.sync GEMM: C[M,N] = A[M,K] @ B[N,K]^T   (inputs pre-rounded tf32)
// CTA 128x128, BK=32, 3-stage cp.async pipeline, 8 warps, fragment
// double-buffering in the ks loop.
// ===========================================================================
#define BK 32
#define APAD 36
#define STAGE_FLOATS (2*128*APAD)
#define NSTAGE 3
#define GEMM_SMEM (NSTAGE*STAGE_FLOATS*4)

__global__ void __launch_bounds__(256, 1) gemm_mma(
    const float* __restrict__ A, const float* __restrict__ B,
    float* __restrict__ C, int M, int N, int K)
{
    extern __shared__ float sm[];
    const uint32_t smb = smem_u32(sm);

    const int tid  = threadIdx.x;
    const int warp = tid >> 5, lane = tid & 31;
    const int wm = warp >> 2, wn = warp & 3;
    const int m0 = blockIdx.y << 7, n0 = blockIdx.x << 7;
    const int q = lane >> 2, r = lane & 3;

    float acc[4][4][4];
#pragma unroll
    for (int i = 0; i < 4; i++)
#pragma unroll
        for (int j = 0; j < 4; j++)
            acc[i][j][0]=acc[i][j][1]=acc[i][j][2]=acc[i][j][3]=0.f;

    int lrow[4], lch[4];
#pragma unroll
    for (int i = 0; i < 4; i++) {
        int idx = tid + i*256;
        lrow[i] = idx >> 3;
        lch[i]  = (idx & 7) << 2;
    }

#define LOAD_TILE(s, kt) do {                                               \
    const uint32_t sA_ = smb + (uint32_t)(s)*STAGE_FLOATS*4;                \
    const uint32_t sB_ = sA_ + 128*APAD*4;                                  \
    const int koff = (kt) * BK;                                             \
    _Pragma("unroll")                                                       \
    for (int i_ = 0; i_ < 4; i_++) {                                        \
        cp_async16(sA_ + (uint32_t)(lrow[i_]*APAD + lch[i_])*4,             \
                   A + (size_t)(m0 + lrow[i_]) * K + koff + lch[i_]);       \
        cp_async16(sB_ + (uint32_t)(lrow[i_]*APAD + lch[i_])*4,             \
                   B + (size_t)(n0 + lrow[i_]) * K + koff + lch[i_]);       \
    } } while (0)

#define LOAD_FRAG(buf, kk) do {                                             \
    _Pragma("unroll")                                                       \
    for (int i_ = 0; i_ < 4; i_++) {                                        \
        const int rowb = wm*64 + i_*16;                                     \
        afr[buf][i_][0] = __float_as_uint(sA[(rowb+q  )*APAD + (kk) + r    ]); \
        afr[buf][i_][1] = __float_as_uint(sA[(rowb+q+8)*APAD + (kk) + r    ]); \
        afr[buf][i_][2] = __float_as_uint(sA[(rowb+q  )*APAD + (kk) + r + 4]); \
        afr[buf][i_][3] = __float_as_uint(sA[(rowb+q+8)*APAD + (kk) + r + 4]); \
    }                                                                       \
    _Pragma("unroll")                                                       \
    for (int j_ = 0; j_ < 4; j_++) {                                        \
        const int colb = wn*32 + j_*8;                                      \
        bfr[buf][j_][0] = __float_as_uint(sB[(colb+q)*APAD + (kk) + r    ]); \
        bfr[buf][j_][1] = __float_as_uint(sB[(colb+q)*APAD + (kk) + r + 4]); \
    } } while (0)

    const int KT = K / BK;
    LOAD_TILE(0, 0); cp_commit();
    LOAD_TILE(1, 1); cp_commit();
    cp_wait1();
    __syncthreads();

    for (int kt = 0; kt < KT; kt++) {
        const int nxt = kt + 2;
        if (nxt < KT) {
            int s = nxt - (nxt/NSTAGE)*NSTAGE;
            LOAD_TILE(s, nxt);
        }
        cp_commit();

        const int cs = kt - (kt/NSTAGE)*NSTAGE;
        const float* sA = sm + cs*STAGE_FLOATS;
        const float* sB = sA + 128*APAD;

        uint32_t afr[2][4][4], bfr[2][4][2];
        LOAD_FRAG(0, 0);
#pragma unroll
        for (int ks = 0; ks < 4; ks++) {
            const int cur = ks & 1;
            if (ks < 3) LOAD_FRAG(cur ^ 1, (ks+1)*8);
#pragma unroll
            for (int i = 0; i < 4; i++)
#pragma unroll
                for (int j = 0; j < 4; j++)
                    mma_tf32(acc[i][j], afr[cur][i], bfr[cur][j]);
        }

        cp_wait1();
        __syncthreads();
    }

#pragma unroll
    for (int i = 0; i < 4; i++) {
        const int row = m0 + wm*64 + i*16 + q;
#pragma unroll
        for (int j = 0; j < 4; j++) {
            const int col = n0 + wn*32 + j*8 + 2*r;
            float2 lo; lo.x = acc[i][j][0]; lo.y = acc[i][j][1];
            float2 hi; hi.x = acc[i][j][2]; hi.y = acc[i][j][3];
            *(float2*)(C + (size_t)row * N + col)       = lo;
            *(float2*)(C + (size_t)(row+8) * N + col)   = hi;
        }
    }
#undef LOAD_TILE
#undef LOAD_FRAG
}

// ---------------------------------------------------------------------------
// fused RoPE on q and k parts of g_qkv (one launch), in-place
// ---------------------------------------------------------------------------
#define ROPE_NQ (MTOT*NH*64)
#define ROPE_NK (MTOT*KVH*64)

__global__ void rope_fused_kernel(float* __restrict__ qkv,
                                  const float* __restrict__ cs,
                                  const float* __restrict__ sn)
{
    int idx = blockIdx.x * 256 + threadIdx.x;
    float* row;
    if (idx < ROPE_NQ) {
        int d = idx & 63;
        int h = (idx >> 6) % NH;
        int t = idx / (NH << 6);
        row = qkv + (size_t)t * QKVW + h * HD;
        int s = t & (SEQ - 1);
        float x1 = row[d], x2 = row[d + 64];
        row[d]      = x1 * cs[s*HD + d]      - x2 * sn[s*HD + d];
        row[d + 64] = x2 * cs[s*HD + d + 64] + x1 * sn[s*HD + d + 64];
    } else if (idx < ROPE_NQ + ROPE_NK) {
        idx -= ROPE_NQ;
        int d = idx & 63;
        int h = (idx >> 6) % KVH;
        int t = idx / (KVH << 6);
        row = qkv + (size_t)t * QKVW + KOFF + h * HD;
        int s = t & (SEQ - 1);
        float x1 = row[d], x2 = row[d + 64];
        row[d]      = x1 * cs[s*HD + d]      - x2 * sn[s*HD + d];
        row[d + 64] = x2 * cs[s*HD + d + 64] + x1 * sn[s*HD + d + 64];
    }
}

// ---------------------------------------------------------------------------
// Flash attention with mma.sync tf32 (causal, GQA). Br=Bc=64, D=128.
// Fragment double-buffering in QK and PV loops.
// ---------------------------------------------------------------------------
#define QKP 132
#define VTP 68
#define SSP 68
#define SQ_OFF  0
#define SK_OFF  (64*QKP)
#define SVT_OFF (SK_OFF + 64*QKP)
#define SS_OFF  (SVT_OFF + 128*VTP)
#define SCR_OFF (SS_OFF + 64*SSP)
#define FLASH_FLOATS (SCR_OFF + 64)
#define FLASH_SMEM (FLASH_FLOATS*4)

__global__ void __launch_bounds__(256, 1) flash_mma_kernel(
    const float* __restrict__ qkv, float* __restrict__ ctx)
{
    extern __shared__ float sm[];
    float* sQ   = sm + SQ_OFF;
    float* sK   = sm + SK_OFF;
    float* sVt  = sm + SVT_OFF;
    float* sS   = sm + SS_OFF;
    float* scorr= sm + SCR_OFF;

    const int b = blockIdx.z, h = blockIdx.y;
    const int qb = (int)gridDim.x - 1 - (int)blockIdx.x;
    const int kh = h >> 2;
    const int tid = threadIdx.x;
    const int warp = tid >> 5, lane = tid & 31;
    const int wm = warp >> 2, wn = warp & 3;
    const int qd = lane >> 2, r4 = lane & 3;

    const float* qbase = qkv + (size_t)(b*SEQ + qb*64) * QKVW + h * HD;
#pragma unroll
    for (int l = 0; l < 8; l++) {
        int idx = tid + l*256;
        int row = idx >> 5, c4 = (idx & 31) << 2;
        float4 t4 = *(const float4*)(qbase + (size_t)row * QKVW + c4);
        t4.x = tf32_round(t4.x); t4.y = tf32_round(t4.y);
        t4.z = tf32_round(t4.z); t4.w = tf32_round(t4.w);
        *(float4*)&sQ[row*QKP + c4] = t4;
    }

    float m_r[8], l_r[8];
#pragma unroll
    for (int i = 0; i < 8; i++) { m_r[i] = -1e30f; l_r[i] = 0.f; }

    float oacc[2][4][4];
#pragma unroll
    for (int i = 0; i < 2; i++)
#pragma unroll
        for (int j = 0; j < 4; j++)
            oacc[i][j][0]=oacc[i][j][1]=oacc[i][j][2]=oacc[i][j][3]=0.f;

    const int grow0 = qb * 64;
    const float sscale = 0.08838834764831845f;

    for (int jb = 0; jb <= qb; jb++) {
        __syncthreads();
        const float* kbase = qkv + (size_t)(b*SEQ + jb*64) * QKVW + KOFF + kh * HD;
        const float* vbase = qkv + (size_t)(b*SEQ + jb*64) * QKVW + VOFF + kh * HD;
#pragma unroll
        for (int l = 0; l < 8; l++) {
            int idx = tid + l*256;
            int row = idx >> 5, c4 = (idx & 31) << 2;
            float4 k4 = *(const float4*)(kbase + (size_t)row * QKVW + c4);
            k4.x = tf32_round(k4.x); k4.y = tf32_round(k4.y);
            k4.z = tf32_round(k4.z); k4.w = tf32_round(k4.w);
            *(float4*)&sK[row*QKP + c4] = k4;
            float4 v4 = *(const float4*)(vbase + (size_t)row * QKVW + c4);
            sVt[(c4+0)*VTP + row] = tf32_round(v4.x);
            sVt[(c4+1)*VTP + row] = tf32_round(v4.y);
            sVt[(c4+2)*VTP + row] = tf32_round(v4.z);
            sVt[(c4+3)*VTP + row] = tf32_round(v4.w);
        }
        __syncthreads();

        // ---- scores: warp tile 32x16, 16 ks steps, frag double-buffered ----
        float sc[2][2][4];
#pragma unroll
        for (int i = 0; i < 2; i++)
#pragma unroll
            for (int j = 0; j < 2; j++)
                sc[i][j][0]=sc[i][j][1]=sc[i][j][2]=sc[i][j][3]=0.f;

        uint32_t qa[2][2][4], kb[2][2][2];
#define QK_FRAG(buf, kk) do {                                               \
    _Pragma("unroll")                                                       \
    for (int i_ = 0; i_ < 2; i_++) {                                        \
        const int rowb = wm*32 + i_*16;                                     \
        qa[buf][i_][0] = __float_as_uint(sQ[(rowb+qd  )*QKP + (kk) + r4    ]); \
        qa[buf][i_][1] = __float_as_uint(sQ[(rowb+qd+8)*QKP + (kk) + r4    ]); \
        qa[buf][i_][2] = __float_as_uint(sQ[(rowb+qd  )*QKP + (kk) + r4 + 4]); \
        qa[buf][i_][3] = __float_as_uint(sQ[(rowb+qd+8)*QKP + (kk) + r4 + 4]); \
    }                                                                       \
    _Pragma("unroll")                                                       \
    for (int j_ = 0; j_ < 2; j_++) {                                        \
        const int colb = wn*16 + j_*8;                                      \
        kb[buf][j_][0] = __float_as_uint(sK[(colb+qd)*QKP + (kk) + r4    ]); \
        kb[buf][j_][1] = __float_as_uint(sK[(colb+qd)*QKP + (kk) + r4 + 4]); \
    } } while (0)

        QK_FRAG(0, 0);
#pragma unroll
        for (int ks = 0; ks < 16; ks++) {
            const int cur = ks & 1;
            if (ks < 15) QK_FRAG(cur ^ 1, (ks+1)*8);
#pragma unroll
            for (int i = 0; i < 2; i++)
#pragma unroll
                for (int j = 0; j < 2; j++)
                    mma_tf32(sc[i][j], qa[cur][i], kb[cur][j]);
        }
#undef QK_FRAG

#pragma unroll
        for (int i = 0; i < 2; i++) {
            const int row = wm*32 + i*16 + qd;
#pragma unroll
            for (int j = 0; j < 2; j++) {
                const int col = wn*16 + j*8 + 2*r4;
                float2 lo; lo.x = sc[i][j][0]*sscale; lo.y = sc[i][j][1]*sscale;
                float2 hi; hi.x = sc[i][j][2]*sscale; hi.y = sc[i][j][3]*sscale;
                *(float2*)&sS[row*SSP + col]     = lo;
                *(float2*)&sS[(row+8)*SSP + col] = hi;
            }
        }
        __syncthreads();

        // ---- softmax (scalar fp32), warp w owns rows 8w..8w+7 ----
        const bool diag = (jb == qb);
        const int col0 = jb * 64;
#pragma unroll
        for (int rr = 0; rr < 8; rr++) {
            int row = warp*8 + rr;
            int grow = grow0 + row;
            float s1 = sS[row*SSP + lane];
            float s2 = sS[row*SSP + 32 + lane];
            if (diag) {
                if (col0 + lane > grow)      s1 = -1e30f;
                if (col0 + 32 + lane > grow) s2 = -1e30f;
            }
            float mx = fmaxf(s1, s2);
#pragma unroll
            for (int o = 16; o > 0; o >>= 1)
                mx = fmaxf(mx, __shfl_xor_sync(0xffffffffu, mx, o));
            float m_new = fmaxf(m_r[rr], mx);
            float corr = __expf(m_r[rr] - m_new);
            float p1 = __expf(s1 - m_new);
            float p2 = __expf(s2 - m_new);
            float ps = p1 + p2;
#pragma unroll
            for (int o = 16; o > 0; o >>= 1)
                ps += __shfl_xor_sync(0xffffffffu, ps, o);
            l_r[rr] = l_r[rr] * corr + ps;
            m_r[rr] = m_new;
            sS[row*SSP + lane]      = tf32_round(p1);
            sS[row*SSP + 32 + lane] = tf32_round(p2);
            if (lane == 0) scorr[row] = corr;
        }
        __syncthreads();

        // ---- PV: warp tile 32x32, 8 ks steps, frag double-buffered ----
        float cr0[2], cr1[2];
#pragma unroll
        for (int i = 0; i < 2; i++) {
            const int row = wm*32 + i*16 + qd;
            cr0[i] = scorr[row];
            cr1[i] = scorr[row+8];
        }
#pragma unroll
        for (int i = 0; i < 2; i++)
#pragma unroll
            for (int j = 0; j < 4; j++) {
                oacc[i][j][0] *= cr0[i]; oacc[i][j][1] *= cr0[i];
                oacc[i][j][2] *= cr1[i]; oacc[i][j][3] *= cr1[i];
            }

        uint32_t pa[2][2][4], vb[2][4][2];
#define PV_FRAG(buf, kk) do {                                               \
    _Pragma("unroll")                                                       \
    for (int i_ = 0; i_ < 2; i_++) {                                        \
        const int rowb = wm*32 + i_*16;                                     \
        pa[buf][i_][0] = __float_as_uint(sS[(rowb+qd  )*SSP + (kk) + r4    ]); \
        pa[buf][i_][1] = __float_as_uint(sS[(rowb+qd+8)*SSP + (kk) + r4    ]); \
        pa[buf][i_][2] = __float_as_uint(sS[(rowb+qd  )*SSP + (kk) + r4 + 4]); \
        pa[buf][i_][3] = __float_as_uint(sS[(rowb+qd+8)*SSP + (kk) + r4 + 4]); \
    }                                                                       \
    _Pragma("unroll")                                                       \
    for (int j_ = 0; j_ < 4; j_++) {                                        \
        const int colb = wn*32 + j_*8;                                      \
        vb[buf][j_][0] = __float_as_uint(sVt[(colb+qd)*VTP + (kk) + r4    ]); \
        vb[buf][j_][1] = __float_as_uint(sVt[(colb+qd)*VTP + (kk) + r4 + 4]); \
    } } while (0)

        PV_FRAG(0, 0);
#pragma unroll
        for (int ks = 0; ks < 8; ks++) {
            const int cur = ks & 1;
            if (ks < 7) PV_FRAG(cur ^ 1, (ks+1)*8);
#pragma unroll
            for (int i = 0; i < 2; i++)
#pragma unroll
                for (int j = 0; j < 4; j++)
                    mma_tf32(oacc[i][j], pa[cur][i], vb[cur][j]);
        }
#undef PV_FRAG
    }

    __syncthreads();
#pragma unroll
    for (int rr = 0; rr < 8; rr++)
        if (lane == 0) scorr[warp*8 + rr] = 1.f / l_r[rr];
    __syncthreads();

#pragma unroll
    for (int i = 0; i < 2; i++) {
        const int row = wm*32 + i*16 + qd;
        const float inv0 = scorr[row], inv1 = scorr[row+8];
        float* d0 = ctx + ((size_t)(b*SEQ + grow0 + row  ) * NH + h) * HD;
        float* d1 = ctx + ((size_t)(b*SEQ + grow0 + row+8) * NH + h) * HD;
#pragma unroll
        for (int j = 0; j < 4; j++) {
            const int col = wn*32 + j*8 + 2*r4;
            float2 lo, hi;
            lo.x = tf32_round(oacc[i][j][0]*inv0);
            lo.y = tf32_round(oacc[i][j][1]*inv0);
            hi.x = tf32_round(oacc[i][j][2]*inv1);
            hi.y = tf32_round(oacc[i][j][3]*inv1);
            *(float2*)(d0 + col) = lo;
            *(float2*)(d1 + col) = hi;
        }
    }
}

// ---------------------------------------------------------------------------
extern "C" void kernel_launch(void* const* d_in, const int* in_sizes, int n_in,
                              void* d_out, int out_size)
{
    const float* hs   = (const float*)d_in[0];
    const float* cosp = (const float*)d_in[1];
    const float* sinp = (const float*)d_in[2];
    const float* Wq   = (const float*)d_in[3];
    const float* Wk   = (const float*)d_in[4];
    const float* Wv   = (const float*)d_in[5];
    const float* Wo   = (const float*)d_in[6];
    float* out = (float*)d_out;

    float *qkv, *ctx, *hs_t, *wqkv, *wo;
    cudaGetSymbolAddress((void**)&qkv,  g_qkv);
    cudaGetSymbolAddress((void**)&ctx,  g_ctx);
    cudaGetSymbolAddress((void**)&hs_t, g_hs);
    cudaGetSymbolAddress((void**)&wqkv, g_wqkv);
    cudaGetSymbolAddress((void**)&wo,   g_wo);

    cudaFuncSetAttribute(gemm_mma, cudaFuncAttributeMaxDynamicSharedMemorySize,
                         (int)GEMM_SMEM);
    cudaFuncSetAttribute(flash_mma_kernel, cudaFuncAttributeMaxDynamicSharedMemorySize,
                         (int)FLASH_SMEM);

    const int M = MTOT;  // 4096

    // 1) fused tf32 pre-rounding of all inputs
    round5_kernel<<<(N4_TOT + 255)/256, 256>>>(hs, Wq, Wk, Wv, Wo,
                                               hs_t, wqkv, wo);

    // 2) fused QKV projection (one launch, N=3072)
    gemm_mma<<<dim3(QKVW/128, M/128), 256, GEMM_SMEM>>>(hs_t, wqkv, qkv,
                                                        M, QKVW, HIDDEN);

    // 3) fused RoPE on q and k parts
    {
        int tot = ROPE_NQ + ROPE_NK;
        rope_fused_kernel<<<(tot + 255)/256, 256>>>(qkv, cosp, sinp);
    }

    // 4) attention (mma.sync tf32 flash)
    flash_mma_kernel<<<dim3(SEQ/64, NH, BATCH), 256, FLASH_SMEM>>>(qkv, ctx);

    // 5) output projection
    gemm_mma<<<dim3(HIDDEN/128, M/128), 256, GEMM_SMEM>>>(ctx, wo, out,
                                                          M, HIDDEN, HIDDEN);
}

// round 9
// speedup vs baseline: 1.2185x; 1.2185x over previous
#include <cuda_runtime.h>
#include <math.h>
#include <stdint.h>

#define BATCH 2
#define SEQ 2048
#define HIDDEN 2048
#define NH 16
#define KVH 4
#define HD 128
#define MTOT (BATCH*SEQ)
#define QKVW 3072
#define KOFF 2048
#define VOFF 2560

// scratch (no allocation allowed -> device globals)
__device__ float g_qkv[MTOT*QKVW];
__device__ float g_ctx[MTOT*HIDDEN];
__device__ float g_hs[MTOT*HIDDEN];
__device__ float g_wqkv[QKVW*HIDDEN];
__device__ float g_wo[HIDDEN*HIDDEN];

// ===========================================================================
// helpers
// ===========================================================================
__device__ __forceinline__ uint32_t smem_u32(const void* p) {
    uint32_t a;
    asm("{ .reg .u64 t; cvta.to.shared.u64 t, %1; cvt.u32.u64 %0, t; }"
        : "=r"(a) : "l"(p));
    return a;
}
__device__ __forceinline__ void cp_async16(uint32_t saddr, const void* gaddr) {
    asm volatile("cp.async.cg.shared.global [%0], [%1], 16;"
                 :: "r"(saddr), "l"(gaddr));
}
__device__ __forceinline__ void cp_commit() {
    asm volatile("cp.async.commit_group;" ::: "memory");
}
__device__ __forceinline__ void cp_wait1() {
    asm volatile("cp.async.wait_group 1;" ::: "memory");
}
__device__ __forceinline__ void cp_wait0() {
    asm volatile("cp.async.wait_group 0;" ::: "memory");
}
__device__ __forceinline__ float tf32_round(float x) {
    uint32_t u;
    asm("cvt.rna.tf32.f32 %0, %1;" : "=r"(u) : "f"(x));
    return __uint_as_float(u);
}
__device__ __forceinline__ void mma_tf32(float* d, const uint32_t* a, const uint32_t* b) {
    asm volatile(
        "mma.sync.aligned.m16n8k8.row.col.f32.tf32.tf32.f32 "
        "{%0,%1,%2,%3}, {%4,%5,%6,%7}, {%8,%9}, {%0,%1,%2,%3};"
        : "+f"(d[0]), "+f"(d[1]), "+f"(d[2]), "+f"(d[3])
        : "r"(a[0]), "r"(a[1]), "r"(a[2]), "r"(a[3]), "r"(b[0]), "r"(b[1]));
}
#define LDSM4(r0,r1,r2,r3,addr)                                              \
    asm volatile("ldmatrix.sync.aligned.m8n8.x4.shared.b16 {%0,%1,%2,%3}, [%4];" \
        : "=r"(r0), "=r"(r1), "=r"(r2), "=r"(r3) : "r"(addr))

// ===========================================================================
// fused tf32 rounding pass: hs -> g_hs, [Wq|Wk|Wv] -> g_wqkv, Wo -> g_wo
// ===========================================================================
#define N4_HS  (MTOT*HIDDEN/4)
#define N4_WQ  (HIDDEN*HIDDEN/4)
#define N4_WKV (KVH*HD*HIDDEN/4)
#define N4_TOT (N4_HS + 2*N4_WQ + 2*N4_WKV)

__global__ void round5_kernel(
    const float* __restrict__ hs, const float* __restrict__ wq,
    const float* __restrict__ wk, const float* __restrict__ wv,
    const float* __restrict__ wo,
    float* __restrict__ dhs, float* __restrict__ dwqkv,
    float* __restrict__ dwo)
{
    int i = blockIdx.x * 256 + threadIdx.x;
    if (i >= N4_TOT) return;
    const float* src; float* dst; int j = i;
    if (j < N4_HS)                  { src = hs; dst = dhs; }
    else if ((j -= N4_HS) < N4_WQ)  { src = wq; dst = dwqkv; }
    else if ((j -= N4_WQ) < N4_WKV) { src = wk; dst = dwqkv + (size_t)KOFF*HIDDEN; }
    else if ((j -= N4_WKV) < N4_WKV){ src = wv; dst = dwqkv + (size_t)VOFF*HIDDEN; }
    else { j -= N4_WKV; src = wo; dst = dwo; }
    float4 v = ((const float4*)src)[j];
    v.x = tf32_round(v.x); v.y = tf32_round(v.y);
    v.z = tf32_round(v.z); v.w = tf32_round(v.w);
    ((float4*)dst)[j] = v;
}

// ===========================================================================
// tf32 mma.sync GEMM with ldmatrix fragment loads.
// CTA 128x128, BK=32, 3-stage cp.async pipeline, 8 warps.
// ===========================================================================
#define BK 32
#define APAD 36
#define STAGE_FLOATS (2*128*APAD)
#define NSTAGE 3
#define GEMM_SMEM (NSTAGE*STAGE_FLOATS*4)

__global__ void __launch_bounds__(256, 1) gemm_mma(
    const float* __restrict__ A, const float* __restrict__ B,
    float* __restrict__ C, int M, int N, int K)
{
    extern __shared__ float sm[];
    const uint32_t smb = smem_u32(sm);

    const int tid  = threadIdx.x;
    const int warp = tid >> 5, lane = tid & 31;
    const int wm = warp >> 2, wn = warp & 3;
    const int m0 = blockIdx.y << 7, n0 = blockIdx.x << 7;
    const int q = lane >> 2, r = lane & 3;

    // ldmatrix per-thread row/col offset (lane -> tile row)
    const int lmt = lane >> 3, lmr = lane & 7;
    const uint32_t lmoff = (uint32_t)((((lmt & 1) << 3 | lmr) * APAD + ((lmt >> 1) << 2)) * 4);

    float acc[4][4][4];
#pragma unroll
    for (int i = 0; i < 4; i++)
#pragma unroll
        for (int j = 0; j < 4; j++)
            acc[i][j][0]=acc[i][j][1]=acc[i][j][2]=acc[i][j][3]=0.f;

    int lrow[4], lch[4];
#pragma unroll
    for (int i = 0; i < 4; i++) {
        int idx = tid + i*256;
        lrow[i] = idx >> 3;
        lch[i]  = (idx & 7) << 2;
    }

#define LOAD_TILE(s, kt) do {                                               \
    const uint32_t sA_ = smb + (uint32_t)(s)*STAGE_FLOATS*4;                \
    const uint32_t sB_ = sA_ + 128*APAD*4;                                  \
    const int koff = (kt) * BK;                                             \
    _Pragma("unroll")                                                       \
    for (int i_ = 0; i_ < 4; i_++) {                                        \
        cp_async16(sA_ + (uint32_t)(lrow[i_]*APAD + lch[i_])*4,             \
                   A + (size_t)(m0 + lrow[i_]) * K + koff + lch[i_]);       \
        cp_async16(sB_ + (uint32_t)(lrow[i_]*APAD + lch[i_])*4,             \
                   B + (size_t)(n0 + lrow[i_]) * K + koff + lch[i_]);       \
    } } while (0)

#define LOAD_FRAG(buf, kk) do {                                             \
    _Pragma("unroll")                                                       \
    for (int i_ = 0; i_ < 4; i_++)                                          \
        LDSM4(afr[buf][i_][0], afr[buf][i_][1], afr[buf][i_][2], afr[buf][i_][3], \
              sAb + (uint32_t)(((wm*64 + i_*16)*APAD + (kk))*4) + lmoff);   \
    LDSM4(bfr[buf][0][0], bfr[buf][1][0], bfr[buf][0][1], bfr[buf][1][1],   \
          sBb + (uint32_t)(((wn*32)*APAD + (kk))*4) + lmoff);               \
    LDSM4(bfr[buf][2][0], bfr[buf][3][0], bfr[buf][2][1], bfr[buf][3][1],   \
          sBb + (uint32_t)(((wn*32 + 16)*APAD + (kk))*4) + lmoff);          \
    } while (0)

    const int KT = K / BK;
    LOAD_TILE(0, 0); cp_commit();
    LOAD_TILE(1, 1); cp_commit();
    cp_wait1();
    __syncthreads();

    for (int kt = 0; kt < KT; kt++) {
        const int nxt = kt + 2;
        if (nxt < KT) {
            int s = nxt - (nxt/NSTAGE)*NSTAGE;
            LOAD_TILE(s, nxt);
        }
        cp_commit();

        const int cs = kt - (kt/NSTAGE)*NSTAGE;
        const uint32_t sAb = smb + (uint32_t)cs*STAGE_FLOATS*4;
        const uint32_t sBb = sAb + 128*APAD*4;

        uint32_t afr[2][4][4], bfr[2][4][2];
        LOAD_FRAG(0, 0);
#pragma unroll
        for (int ks = 0; ks < 4; ks++) {
            const int cur = ks & 1;
            if (ks < 3) LOAD_FRAG(cur ^ 1, (ks+1)*8);
#pragma unroll
            for (int i = 0; i < 4; i++)
#pragma unroll
                for (int j = 0; j < 4; j++)
                    mma_tf32(acc[i][j], afr[cur][i], bfr[cur][j]);
        }

        cp_wait1();
        __syncthreads();
    }

#pragma unroll
    for (int i = 0; i < 4; i++) {
        const int row = m0 + wm*64 + i*16 + q;
#pragma unroll
        for (int j = 0; j < 4; j++) {
            const int col = n0 + wn*32 + j*8 + 2*r;
            float2 lo; lo.x = acc[i][j][0]; lo.y = acc[i][j][1];
            float2 hi; hi.x = acc[i][j][2]; hi.y = acc[i][j][3];
            *(float2*)(C + (size_t)row * N + col)       = lo;
            *(float2*)(C + (size_t)(row+8) * N + col)   = hi;
        }
    }
#undef LOAD_TILE
#undef LOAD_FRAG
}

// ---------------------------------------------------------------------------
// fused RoPE + tf32 rounding: q (rope+round), k (rope+round), v (round only)
// ---------------------------------------------------------------------------
#define ROPE_NQ (MTOT*NH*64)
#define ROPE_NK (MTOT*KVH*64)
#define ROPE_NV (MTOT*128)           // v processed as float4
#define ROPE_TOT (ROPE_NQ + ROPE_NK + ROPE_NV)

__global__ void rope_round_kernel(float* __restrict__ qkv,
                                  const float* __restrict__ cs,
                                  const float* __restrict__ sn)
{
    int idx = blockIdx.x * 256 + threadIdx.x;
    if (idx < ROPE_NQ) {
        int d = idx & 63;
        int h = (idx >> 6) % NH;
        int t = idx / (NH << 6);
        float* row = qkv + (size_t)t * QKVW + h * HD;
        int s = t & (SEQ - 1);
        float x1 = row[d], x2 = row[d + 64];
        row[d]      = tf32_round(x1 * cs[s*HD + d]      - x2 * sn[s*HD + d]);
        row[d + 64] = tf32_round(x2 * cs[s*HD + d + 64] + x1 * sn[s*HD + d + 64]);
    } else if ((idx -= ROPE_NQ) < ROPE_NK) {
        int d = idx & 63;
        int h = (idx >> 6) % KVH;
        int t = idx / (KVH << 6);
        float* row = qkv + (size_t)t * QKVW + KOFF + h * HD;
        int s = t & (SEQ - 1);
        float x1 = row[d], x2 = row[d + 64];
        row[d]      = tf32_round(x1 * cs[s*HD + d]      - x2 * sn[s*HD + d]);
        row[d + 64] = tf32_round(x2 * cs[s*HD + d + 64] + x1 * sn[s*HD + d + 64]);
    } else if ((idx -= ROPE_NK) < ROPE_NV) {
        int t = idx >> 7, c4 = (idx & 127) << 2;
        float* p = qkv + (size_t)t * QKVW + VOFF + c4;
        float4 v = *(float4*)p;
        v.x = tf32_round(v.x); v.y = tf32_round(v.y);
        v.z = tf32_round(v.z); v.w = tf32_round(v.w);
        *(float4*)p = v;
    }
}

// ---------------------------------------------------------------------------
// Flash attention, mma.sync tf32 + ldmatrix. Br=128, Bc=64, D=128.
// 512 threads (16 warps = 4/SMSP). Warp grid 4x4.
// ---------------------------------------------------------------------------
#define FQKP 132
#define FVP 68
#define FSP 68
#define FSQ 0
#define FSK (128*FQKP)
#define FSV (FSK + 64*FQKP)
#define FSS (FSV + 128*FVP)
#define FSC (FSS + 128*FSP)
#define FLASH_FLOATS (FSC + 128)
#define FLASH_SMEM (FLASH_FLOATS*4)

__global__ void __launch_bounds__(512, 1) flash_mma_kernel(
    const float* __restrict__ qkv, float* __restrict__ ctx)
{
    extern __shared__ float sm[];
    const uint32_t smb = smem_u32(sm);
    float* sS   = sm + FSS;
    float* scorr= sm + FSC;

    const int b = blockIdx.z, h = blockIdx.y;
    const int qb = (int)gridDim.x - 1 - (int)blockIdx.x;   // long CTAs first
    const int kh = h >> 2;
    const int tid = threadIdx.x;
    const int warp = tid >> 5, lane = tid & 31;
    const int wm = warp >> 2, wn = warp & 3;               // 4 x 4 warp grid
    const int qd = lane >> 2, r4 = lane & 3;

    // ldmatrix per-thread offsets
    const int lmt = lane >> 3, lmr = lane & 7;
    const int lmrow = ((lmt & 1) << 3) | lmr;
    const int lmcol = (lmt >> 1) << 2;
    const uint32_t lmQK = (uint32_t)((lmrow*FQKP + lmcol) * 4);
    const uint32_t lmS  = (uint32_t)((lmrow*FSP  + lmcol) * 4);

    // ---- Q tile via cp.async (128 x 128, values pre-rounded) ----
    const float* qbase = qkv + (size_t)(b*SEQ + qb*128) * QKVW + h * HD;
#pragma unroll
    for (int l = 0; l < 8; l++) {
        int idx = tid + l*512;
        int row = idx >> 5, c4 = (idx & 31) << 2;
        cp_async16(smb + (uint32_t)((FSQ + row*FQKP + c4)*4),
                   qbase + (size_t)row * QKVW + c4);
    }
    cp_commit();

    // V store mapping (conflict-free transpose): block bi = warp + l*16
    // j0 = (bi&3)*16, c0 = (bi>>2)*2;  j = j0 + (lane>>1), c = c0 + (lane&1)

    float m_r[8], l_r[8];
#pragma unroll
    for (int i = 0; i < 8; i++) { m_r[i] = -1e30f; l_r[i] = 0.f; }

    float oacc[2][4][4];
#pragma unroll
    for (int i = 0; i < 2; i++)
#pragma unroll
        for (int j = 0; j < 4; j++)
            oacc[i][j][0]=oacc[i][j][1]=oacc[i][j][2]=oacc[i][j][3]=0.f;

    const int grow0 = qb * 128;
    const float sscale = 0.08838834764831845f;
    const int njb = 2*qb + 2;

    for (int jb = 0; jb < njb; jb++) {
        __syncthreads();   // prior PV done with sS/sVt; sK free
        const float* kbase = qkv + (size_t)(b*SEQ + jb*64) * QKVW + KOFF + kh * HD;
        const float* vbase = qkv + (size_t)(b*SEQ + jb*64) * QKVW + VOFF + kh * HD;
        // K via cp.async (64 x 128)
#pragma unroll
        for (int l = 0; l < 4; l++) {
            int idx = tid + l*512;
            int row = idx >> 5, c4 = (idx & 31) << 2;
            cp_async16(smb + (uint32_t)((FSK + row*FQKP + c4)*4),
                       kbase + (size_t)row * QKVW + c4);
        }
        cp_commit();
        // V transposed (LDG 32B-sector coalesced, STS conflict-free)
#pragma unroll
        for (int l = 0; l < 4; l++) {
            int bi = warp + l*16;
            int j = ((bi & 3) << 4) + (lane >> 1);
            int c = ((bi >> 2) << 1) + (lane & 1);
            float4 v4 = *(const float4*)(vbase + (size_t)j * QKVW + (c << 2));
            sm[FSV + (4*c+0)*FVP + j] = v4.x;
            sm[FSV + (4*c+1)*FVP + j] = v4.y;
            sm[FSV + (4*c+2)*FVP + j] = v4.z;
            sm[FSV + (4*c+3)*FVP + j] = v4.w;
        }
        cp_wait0();
        __syncthreads();

        // ---- QK: warp tile 32x16 at (wm*32, wn*16), 16 ks steps ----
        float sc[2][2][4];
#pragma unroll
        for (int i = 0; i < 2; i++)
#pragma unroll
            for (int j = 0; j < 2; j++)
                sc[i][j][0]=sc[i][j][1]=sc[i][j][2]=sc[i][j][3]=0.f;

        const uint32_t aQ0 = smb + (uint32_t)((FSQ + (wm*32)*FQKP)*4) + lmQK;
        const uint32_t bK0 = smb + (uint32_t)((FSK + (wn*16)*FQKP)*4) + lmQK;
#pragma unroll
        for (int ks = 0; ks < 16; ks++) {
            const uint32_t kk4 = (uint32_t)(ks*32);
            uint32_t qa[2][4], kb[2][2];
            LDSM4(qa[0][0], qa[0][1], qa[0][2], qa[0][3], aQ0 + kk4);
            LDSM4(qa[1][0], qa[1][1], qa[1][2], qa[1][3], aQ0 + (uint32_t)(16*FQKP*4) + kk4);
            LDSM4(kb[0][0], kb[1][0], kb[0][1], kb[1][1], bK0 + kk4);
#pragma unroll
            for (int i = 0; i < 2; i++)
#pragma unroll
                for (int j = 0; j < 2; j++)
                    mma_tf32(sc[i][j], qa[i], kb[j]);
        }
#pragma unroll
        for (int i = 0; i < 2; i++) {
            const int row = wm*32 + i*16 + qd;
#pragma unroll
            for (int j = 0; j < 2; j++) {
                const int col = wn*16 + j*8 + 2*r4;
                float2 lo; lo.x = sc[i][j][0]*sscale; lo.y = sc[i][j][1]*sscale;
                float2 hi; hi.x = sc[i][j][2]*sscale; hi.y = sc[i][j][3]*sscale;
                *(float2*)&sS[row*FSP + col]     = lo;
                *(float2*)&sS[(row+8)*FSP + col] = hi;
            }
        }
        __syncthreads();

        // ---- softmax (scalar fp32), warp owns rows warp*8..+7 ----
        const bool diag = (jb >= 2*qb);
        const int col0 = jb * 64;
#pragma unroll
        for (int rr = 0; rr < 8; rr++) {
            int row = warp*8 + rr;
            int grow = grow0 + row;
            float s1 = sS[row*FSP + lane];
            float s2 = sS[row*FSP + 32 + lane];
            if (diag) {
                if (col0 + lane > grow)      s1 = -1e30f;
                if (col0 + 32 + lane > grow) s2 = -1e30f;
            }
            float mx = fmaxf(s1, s2);
#pragma unroll
            for (int o = 16; o > 0; o >>= 1)
                mx = fmaxf(mx, __shfl_xor_sync(0xffffffffu, mx, o));
            float m_new = fmaxf(m_r[rr], mx);
            float corr = __expf(m_r[rr] - m_new);
            float p1 = __expf(s1 - m_new);
            float p2 = __expf(s2 - m_new);
            float ps = p1 + p2;
#pragma unroll
            for (int o = 16; o > 0; o >>= 1)
                ps += __shfl_xor_sync(0xffffffffu, ps, o);
            l_r[rr] = l_r[rr] * corr + ps;
            m_r[rr] = m_new;
            sS[row*FSP + lane]      = tf32_round(p1);
            sS[row*FSP + 32 + lane] = tf32_round(p2);
            if (lane == 0) scorr[row] = corr;
        }
        __syncthreads();

        // ---- PV: warp tile 32x32 at (wm*32, wn*32), 8 ks steps ----
        float cr0[2], cr1[2];
#pragma unroll
        for (int i = 0; i < 2; i++) {
            const int row = wm*32 + i*16 + qd;
            cr0[i] = scorr[row];
            cr1[i] = scorr[row+8];
        }
#pragma unroll
        for (int i = 0; i < 2; i++)
#pragma unroll
            for (int j = 0; j < 4; j++) {
                oacc[i][j][0] *= cr0[i]; oacc[i][j][1] *= cr0[i];
                oacc[i][j][2] *= cr1[i]; oacc[i][j][3] *= cr1[i];
            }

        const uint32_t aS0 = smb + (uint32_t)((FSS + (wm*32)*FSP)*4) + lmS;
        const uint32_t bV0 = smb + (uint32_t)((FSV + (wn*32)*FVP)*4) + lmS;
#pragma unroll
        for (int ks = 0; ks < 8; ks++) {
            const uint32_t kk4 = (uint32_t)(ks*32);
            uint32_t pa[2][4], vb[4][2];
            LDSM4(pa[0][0], pa[0][1], pa[0][2], pa[0][3], aS0 + kk4);
            LDSM4(pa[1][0], pa[1][1], pa[1][2], pa[1][3], aS0 + (uint32_t)(16*FSP*4) + kk4);
            LDSM4(vb[0][0], vb[1][0], vb[0][1], vb[1][1], bV0 + kk4);
            LDSM4(vb[2][0], vb[3][0], vb[2][1], vb[3][1], bV0 + (uint32_t)(16*FVP*4) + kk4);
#pragma unroll
            for (int i = 0; i < 2; i++)
#pragma unroll
                for (int j = 0; j < 4; j++)
                    mma_tf32(oacc[i][j], pa[i], vb[j]);
        }
    }

    // publish 1/l per row
    __syncthreads();
#pragma unroll
    for (int rr = 0; rr < 8; rr++)
        if (lane == 0) scorr[warp*8 + rr] = 1.f / l_r[rr];
    __syncthreads();

    // epilogue (tf32-rounded for the tf32 O-projection)
#pragma unroll
    for (int i = 0; i < 2; i++) {
        const int row = wm*32 + i*16 + qd;
        const float inv0 = scorr[row], inv1 = scorr[row+8];
        float* d0 = ctx + ((size_t)(b*SEQ + grow0 + row  ) * NH + h) * HD;
        float* d1 = ctx + ((size_t)(b*SEQ + grow0 + row+8) * NH + h) * HD;
#pragma unroll
        for (int j = 0; j < 4; j++) {
            const int col = wn*32 + j*8 + 2*r4;
            float2 lo, hi;
            lo.x = tf32_round(oacc[i][j][0]*inv0);
            lo.y = tf32_round(oacc[i][j][1]*inv0);
            hi.x = tf32_round(oacc[i][j][2]*inv1);
            hi.y = tf32_round(oacc[i][j][3]*inv1);
            *(float2*)(d0 + col) = lo;
            *(float2*)(d1 + col) = hi;
        }
    }
}

// ---------------------------------------------------------------------------
extern "C" void kernel_launch(void* const* d_in, const int* in_sizes, int n_in,
                              void* d_out, int out_size)
{
    const float* hs   = (const float*)d_in[0];
    const float* cosp = (const float*)d_in[1];
    const float* sinp = (const float*)d_in[2];
    const float* Wq   = (const float*)d_in[3];
    const float* Wk   = (const float*)d_in[4];
    const float* Wv   = (const float*)d_in[5];
    const float* Wo   = (const float*)d_in[6];
    float* out = (float*)d_out;

    float *qkv, *ctx, *hs_t, *wqkv, *wo;
    cudaGetSymbolAddress((void**)&qkv,  g_qkv);
    cudaGetSymbolAddress((void**)&ctx,  g_ctx);
    cudaGetSymbolAddress((void**)&hs_t, g_hs);
    cudaGetSymbolAddress((void**)&wqkv, g_wqkv);
    cudaGetSymbolAddress((void**)&wo,   g_wo);

    cudaFuncSetAttribute(gemm_mma, cudaFuncAttributeMaxDynamicSharedMemorySize,
                         (int)GEMM_SMEM);
    cudaFuncSetAttribute(flash_mma_kernel, cudaFuncAttributeMaxDynamicSharedMemorySize,
                         (int)FLASH_SMEM);

    const int M = MTOT;  // 4096

    // 1) fused tf32 pre-rounding of all inputs
    round5_kernel<<<(N4_TOT + 255)/256, 256>>>(hs, Wq, Wk, Wv, Wo,
                                               hs_t, wqkv, wo);

    // 2) fused QKV projection
    gemm_mma<<<dim3(QKVW/128, M/128), 256, GEMM_SMEM>>>(hs_t, wqkv, qkv,
                                                        M, QKVW, HIDDEN);

    // 3) fused RoPE + rounding of q/k/v
    rope_round_kernel<<<(ROPE_TOT + 255)/256, 256>>>(qkv, cosp, sinp);

    // 4) attention (Br=128, ldmatrix + mma.sync)
    flash_mma_kernel<<<dim3(SEQ/128, NH, BATCH), 512, FLASH_SMEM>>>(qkv, ctx);

    // 5) output projection
    gemm_mma<<<dim3(HIDDEN/128, M/128), 256, GEMM_SMEM>>>(ctx, wo, out,
                                                          M, HIDDEN, HIDDEN);
}

// round 10
// speedup vs baseline: 1.2718x; 1.0437x over previous
#include <cuda_runtime.h>
#include <math.h>
#include <stdint.h>

#define BATCH 2
#define SEQ 2048
#define HIDDEN 2048
#define NH 16
#define KVH 4
#define HD 128
#define MTOT (BATCH*SEQ)
#define QKVW 3072
#define KOFF 2048
#define VOFF 2560

// scratch (no allocation allowed -> device globals)
__device__ float g_qkv[MTOT*QKVW];
__device__ float g_ctx[MTOT*HIDDEN];
__device__ float g_hs[MTOT*HIDDEN];
__device__ float g_wqkv[QKVW*HIDDEN];
__device__ float g_wo[HIDDEN*HIDDEN];

// ===========================================================================
// helpers
// ===========================================================================
__device__ __forceinline__ uint32_t smem_u32(const void* p) {
    uint32_t a;
    asm("{ .reg .u64 t; cvta.to.shared.u64 t, %1; cvt.u32.u64 %0, t; }"
        : "=r"(a) : "l"(p));
    return a;
}
__device__ __forceinline__ void cp_async16(uint32_t saddr, const void* gaddr) {
    asm volatile("cp.async.cg.shared.global [%0], [%1], 16;"
                 :: "r"(saddr), "l"(gaddr));
}
__device__ __forceinline__ void cp_commit() {
    asm volatile("cp.async.commit_group;" ::: "memory");
}
__device__ __forceinline__ void cp_wait1() {
    asm volatile("cp.async.wait_group 1;" ::: "memory");
}
__device__ __forceinline__ void cp_wait0() {
    asm volatile("cp.async.wait_group 0;" ::: "memory");
}
__device__ __forceinline__ float tf32_round(float x) {
    uint32_t u;
    asm("cvt.rna.tf32.f32 %0, %1;" : "=r"(u) : "f"(x));
    return __uint_as_float(u);
}
__device__ __forceinline__ void mma_tf32(float* d, const uint32_t* a, const uint32_t* b) {
    asm volatile(
        "mma.sync.aligned.m16n8k8.row.col.f32.tf32.tf32.f32 "
        "{%0,%1,%2,%3}, {%4,%5,%6,%7}, {%8,%9}, {%0,%1,%2,%3};"
        : "+f"(d[0]), "+f"(d[1]), "+f"(d[2]), "+f"(d[3])
        : "r"(a[0]), "r"(a[1]), "r"(a[2]), "r"(a[3]), "r"(b[0]), "r"(b[1]));
}
#define LDSM4(r0,r1,r2,r3,addr)                                              \
    asm volatile("ldmatrix.sync.aligned.m8n8.x4.shared.b16 {%0,%1,%2,%3}, [%4];" \
        : "=r"(r0), "=r"(r1), "=r"(r2), "=r"(r3) : "r"(addr))

// ===========================================================================
// fused tf32 rounding pass: hs -> g_hs, [Wq|Wk|Wv] -> g_wqkv, Wo -> g_wo
// ===========================================================================
#define N4_HS  (MTOT*HIDDEN/4)
#define N4_WQ  (HIDDEN*HIDDEN/4)
#define N4_WKV (KVH*HD*HIDDEN/4)
#define N4_TOT (N4_HS + 2*N4_WQ + 2*N4_WKV)

__global__ void round5_kernel(
    const float* __restrict__ hs, const float* __restrict__ wq,
    const float* __restrict__ wk, const float* __restrict__ wv,
    const float* __restrict__ wo,
    float* __restrict__ dhs, float* __restrict__ dwqkv,
    float* __restrict__ dwo)
{
    int i = blockIdx.x * 256 + threadIdx.x;
    if (i >= N4_TOT) return;
    const float* src; float* dst; int j = i;
    if (j < N4_HS)                  { src = hs; dst = dhs; }
    else if ((j -= N4_HS) < N4_WQ)  { src = wq; dst = dwqkv; }
    else if ((j -= N4_WQ) < N4_WKV) { src = wk; dst = dwqkv + (size_t)KOFF*HIDDEN; }
    else if ((j -= N4_WKV) < N4_WKV){ src = wv; dst = dwqkv + (size_t)VOFF*HIDDEN; }
    else { j -= N4_WKV; src = wo; dst = dwo; }
    float4 v = ((const float4*)src)[j];
    v.x = tf32_round(v.x); v.y = tf32_round(v.y);
    v.z = tf32_round(v.z); v.w = tf32_round(v.w);
    ((float4*)dst)[j] = v;
}

// ===========================================================================
// tf32 mma.sync GEMM with ldmatrix. CTA 128x256, BK=32, 3-stage cp.async,
// 512 threads (16 warps, 2x8 grid, warp tile 64x32). N multiple of 256.
// ===========================================================================
#define BK 32
#define APAD 36
#define STAGE_FLOATS ((128+256)*APAD)       // A tile then B tile
#define NSTAGE 3
#define GEMM_SMEM (NSTAGE*STAGE_FLOATS*4)

__global__ void __launch_bounds__(512, 1) gemm_mma(
    const float* __restrict__ A, const float* __restrict__ B,
    float* __restrict__ C, int M, int N, int K)
{
    extern __shared__ float sm[];
    const uint32_t smb = smem_u32(sm);

    const int tid  = threadIdx.x;
    const int warp = tid >> 5, lane = tid & 31;
    const int wm = warp >> 3, wn = warp & 7;     // 2 x 8 warp grid
    const int m0 = blockIdx.y << 7, n0 = blockIdx.x << 8;
    const int q = lane >> 2, r = lane & 3;

    // ldmatrix per-thread row/col offset
    const int lmt = lane >> 3, lmr = lane & 7;
    const uint32_t lmoff = (uint32_t)((((lmt & 1) << 3 | lmr) * APAD + ((lmt >> 1) << 2)) * 4);

    float acc[4][4][4];
#pragma unroll
    for (int i = 0; i < 4; i++)
#pragma unroll
        for (int j = 0; j < 4; j++)
            acc[i][j][0]=acc[i][j][1]=acc[i][j][2]=acc[i][j][3]=0.f;

    // A: 1024 chunks (2/thread), B: 2048 chunks (4/thread)
    const int arow0 = tid >> 3, ach = (tid & 7) << 2;    // + l*64 rows

#define LOAD_TILE(s, kt) do {                                               \
    const uint32_t sA_ = smb + (uint32_t)(s)*STAGE_FLOATS*4;                \
    const uint32_t sB_ = sA_ + 128*APAD*4;                                  \
    const int koff = (kt) * BK;                                             \
    _Pragma("unroll")                                                       \
    for (int l_ = 0; l_ < 2; l_++) {                                        \
        int row = arow0 + l_*64;                                            \
        cp_async16(sA_ + (uint32_t)(row*APAD + ach)*4,                      \
                   A + (size_t)(m0 + row) * K + koff + ach);                \
    }                                                                       \
    _Pragma("unroll")                                                       \
    for (int l_ = 0; l_ < 4; l_++) {                                        \
        int row = arow0 + l_*64;                                            \
        cp_async16(sB_ + (uint32_t)(row*APAD + ach)*4,                      \
                   B + (size_t)(n0 + row) * K + koff + ach);                \
    } } while (0)

    const int KT = K / BK;
    LOAD_TILE(0, 0); cp_commit();
    LOAD_TILE(1, 1); cp_commit();
    cp_wait1();
    __syncthreads();

    for (int kt = 0; kt < KT; kt++) {
        const int nxt = kt + 2;
        if (nxt < KT) {
            int s = nxt - (nxt/NSTAGE)*NSTAGE;
            LOAD_TILE(s, nxt);
        }
        cp_commit();

        const int cs = kt - (kt/NSTAGE)*NSTAGE;
        const uint32_t sAb = smb + (uint32_t)cs*STAGE_FLOATS*4;
        const uint32_t sBb = sAb + 128*APAD*4;

#pragma unroll
        for (int ks = 0; ks < 4; ks++) {
            const int kk = ks * 8;
            uint32_t afr[4][4], bfr[4][2];
#pragma unroll
            for (int i = 0; i < 4; i++)
                LDSM4(afr[i][0], afr[i][1], afr[i][2], afr[i][3],
                      sAb + (uint32_t)(((wm*64 + i*16)*APAD + kk)*4) + lmoff);
            LDSM4(bfr[0][0], bfr[1][0], bfr[0][1], bfr[1][1],
                  sBb + (uint32_t)(((wn*32)*APAD + kk)*4) + lmoff);
            LDSM4(bfr[2][0], bfr[3][0], bfr[2][1], bfr[3][1],
                  sBb + (uint32_t)(((wn*32 + 16)*APAD + kk)*4) + lmoff);
#pragma unroll
            for (int i = 0; i < 4; i++)
#pragma unroll
                for (int j = 0; j < 4; j++)
                    mma_tf32(acc[i][j], afr[i], bfr[j]);
        }

        cp_wait1();
        __syncthreads();
    }

#pragma unroll
    for (int i = 0; i < 4; i++) {
        const int row = m0 + wm*64 + i*16 + q;
#pragma unroll
        for (int j = 0; j < 4; j++) {
            const int col = n0 + wn*32 + j*8 + 2*r;
            float2 lo; lo.x = acc[i][j][0]; lo.y = acc[i][j][1];
            float2 hi; hi.x = acc[i][j][2]; hi.y = acc[i][j][3];
            *(float2*)(C + (size_t)row * N + col)       = lo;
            *(float2*)(C + (size_t)(row+8) * N + col)   = hi;
        }
    }
#undef LOAD_TILE
}

// ---------------------------------------------------------------------------
// fused RoPE + tf32 rounding: q (rope+round), k (rope+round), v (round only)
// ---------------------------------------------------------------------------
#define ROPE_NQ (MTOT*NH*64)
#define ROPE_NK (MTOT*KVH*64)
#define ROPE_NV (MTOT*128)
#define ROPE_TOT (ROPE_NQ + ROPE_NK + ROPE_NV)

__global__ void rope_round_kernel(float* __restrict__ qkv,
                                  const float* __restrict__ cs,
                                  const float* __restrict__ sn)
{
    int idx = blockIdx.x * 256 + threadIdx.x;
    if (idx < ROPE_NQ) {
        int d = idx & 63;
        int h = (idx >> 6) % NH;
        int t = idx / (NH << 6);
        float* row = qkv + (size_t)t * QKVW + h * HD;
        int s = t & (SEQ - 1);
        float x1 = row[d], x2 = row[d + 64];
        row[d]      = tf32_round(x1 * cs[s*HD + d]      - x2 * sn[s*HD + d]);
        row[d + 64] = tf32_round(x2 * cs[s*HD + d + 64] + x1 * sn[s*HD + d + 64]);
    } else if ((idx -= ROPE_NQ) < ROPE_NK) {
        int d = idx & 63;
        int h = (idx >> 6) % KVH;
        int t = idx / (KVH << 6);
        float* row = qkv + (size_t)t * QKVW + KOFF + h * HD;
        int s = t & (SEQ - 1);
        float x1 = row[d], x2 = row[d + 64];
        row[d]      = tf32_round(x1 * cs[s*HD + d]      - x2 * sn[s*HD + d]);
        row[d + 64] = tf32_round(x2 * cs[s*HD + d + 64] + x1 * sn[s*HD + d + 64]);
    } else if ((idx -= ROPE_NK) < ROPE_NV) {
        int t = idx >> 7, c4 = (idx & 127) << 2;
        float* p = qkv + (size_t)t * QKVW + VOFF + c4;
        float4 v = *(float4*)p;
        v.x = tf32_round(v.x); v.y = tf32_round(v.y);
        v.z = tf32_round(v.z); v.w = tf32_round(v.w);
        *(float4*)p = v;
    }
}

// ---------------------------------------------------------------------------
// Flash attention, mma.sync tf32 + ldmatrix. Br=128, Bc=64, D=128.
// 512 threads (16 warps). V transpose via conflict-free float4 STS.
// ---------------------------------------------------------------------------
#define FQKP 132
#define FVP 68
#define FSP 68
#define FSQ 0
#define FSK (128*FQKP)
#define FSV (FSK + 64*FQKP)
#define FSS (FSV + 128*FVP)
#define FSC (FSS + 128*FSP)
#define FLASH_FLOATS (FSC + 128)
#define FLASH_SMEM (FLASH_FLOATS*4)

__global__ void __launch_bounds__(512, 1) flash_mma_kernel(
    const float* __restrict__ qkv, float* __restrict__ ctx)
{
    extern __shared__ float sm[];
    const uint32_t smb = smem_u32(sm);
    float* sS   = sm + FSS;
    float* scorr= sm + FSC;

    const int b = blockIdx.z, h = blockIdx.y;
    const int qb = (int)gridDim.x - 1 - (int)blockIdx.x;   // long CTAs first
    const int kh = h >> 2;
    const int tid = threadIdx.x;
    const int warp = tid >> 5, lane = tid & 31;
    const int wm = warp >> 2, wn = warp & 3;
    const int qd = lane >> 2, r4 = lane & 3;

    const int lmt = lane >> 3, lmr = lane & 7;
    const int lmrow = ((lmt & 1) << 3) | lmr;
    const int lmcol = (lmt >> 1) << 2;
    const uint32_t lmQK = (uint32_t)((lmrow*FQKP + lmcol) * 4);
    const uint32_t lmS  = (uint32_t)((lmrow*FSP  + lmcol) * 4);

    // V transpose mapping: thread -> 4(j) x 4(d) block
    const int vjc = tid & 15;           // j0 = 4*vjc
    const int vdc = tid >> 4;           // d0 = 4*vdc

    // ---- Q tile via cp.async ----
    const float* qbase = qkv + (size_t)(b*SEQ + qb*128) * QKVW + h * HD;
#pragma unroll
    for (int l = 0; l < 8; l++) {
        int idx = tid + l*512;
        int row = idx >> 5, c4 = (idx & 31) << 2;
        cp_async16(smb + (uint32_t)((FSQ + row*FQKP + c4)*4),
                   qbase + (size_t)row * QKVW + c4);
    }
    cp_commit();

    float m_r[8], l_r[8];
#pragma unroll
    for (int i = 0; i < 8; i++) { m_r[i] = -1e30f; l_r[i] = 0.f; }

    float oacc[2][4][4];
#pragma unroll
    for (int i = 0; i < 2; i++)
#pragma unroll
        for (int j = 0; j < 4; j++)
            oacc[i][j][0]=oacc[i][j][1]=oacc[i][j][2]=oacc[i][j][3]=0.f;

    const int grow0 = qb * 128;
    const float sscale = 0.08838834764831845f;
    const int njb = 2*qb + 2;

    for (int jb = 0; jb < njb; jb++) {
        __syncthreads();
        const float* kbase = qkv + (size_t)(b*SEQ + jb*64) * QKVW + KOFF + kh * HD;
        const float* vbase = qkv + (size_t)(b*SEQ + jb*64) * QKVW + VOFF + kh * HD;
        // K via cp.async (64 x 128)
#pragma unroll
        for (int l = 0; l < 4; l++) {
            int idx = tid + l*512;
            int row = idx >> 5, c4 = (idx & 31) << 2;
            cp_async16(smb + (uint32_t)((FSK + row*FQKP + c4)*4),
                       kbase + (size_t)row * QKVW + c4);
        }
        cp_commit();
        // V transposed: 4 LDG.128 + 4 STS.128 per thread, conflict-free
        {
            const int j0 = vjc << 2, d0 = vdc << 2;
            float4 v0 = *(const float4*)(vbase + (size_t)(j0+0) * QKVW + d0);
            float4 v1 = *(const float4*)(vbase + (size_t)(j0+1) * QKVW + d0);
            float4 v2 = *(const float4*)(vbase + (size_t)(j0+2) * QKVW + d0);
            float4 v3 = *(const float4*)(vbase + (size_t)(j0+3) * QKVW + d0);
            float4 t;
            t.x=v0.x; t.y=v1.x; t.z=v2.x; t.w=v3.x;
            *(float4*)&sm[FSV + (d0+0)*FVP + j0] = t;
            t.x=v0.y; t.y=v1.y; t.z=v2.y; t.w=v3.y;
            *(float4*)&sm[FSV + (d0+1)*FVP + j0] = t;
            t.x=v0.z; t.y=v1.z; t.z=v2.z; t.w=v3.z;
            *(float4*)&sm[FSV + (d0+2)*FVP + j0] = t;
            t.x=v0.w; t.y=v1.w; t.z=v2.w; t.w=v3.w;
            *(float4*)&sm[FSV + (d0+3)*FVP + j0] = t;
        }
        cp_wait0();
        __syncthreads();

        // ---- QK: warp tile 32x16, 16 ks steps ----
        float sc[2][2][4];
#pragma unroll
        for (int i = 0; i < 2; i++)
#pragma unroll
            for (int j = 0; j < 2; j++)
                sc[i][j][0]=sc[i][j][1]=sc[i][j][2]=sc[i][j][3]=0.f;

        const uint32_t aQ0 = smb + (uint32_t)((FSQ + (wm*32)*FQKP)*4) + lmQK;
        const uint32_t bK0 = smb + (uint32_t)((FSK + (wn*16)*FQKP)*4) + lmQK;
#pragma unroll
        for (int ks = 0; ks < 16; ks++) {
            const uint32_t kk4 = (uint32_t)(ks*32);
            uint32_t qa[2][4], kb[2][2];
            LDSM4(qa[0][0], qa[0][1], qa[0][2], qa[0][3], aQ0 + kk4);
            LDSM4(qa[1][0], qa[1][1], qa[1][2], qa[1][3], aQ0 + (uint32_t)(16*FQKP*4) + kk4);
            LDSM4(kb[0][0], kb[1][0], kb[0][1], kb[1][1], bK0 + kk4);
#pragma unroll
            for (int i = 0; i < 2; i++)
#pragma unroll
                for (int j = 0; j < 2; j++)
                    mma_tf32(sc[i][j], qa[i], kb[j]);
        }
#pragma unroll
        for (int i = 0; i < 2; i++) {
            const int row = wm*32 + i*16 + qd;
#pragma unroll
            for (int j = 0; j < 2; j++) {
                const int col = wn*16 + j*8 + 2*r4;
                float2 lo; lo.x = sc[i][j][0]*sscale; lo.y = sc[i][j][1]*sscale;
                float2 hi; hi.x = sc[i][j][2]*sscale; hi.y = sc[i][j][3]*sscale;
                *(float2*)&sS[row*FSP + col]     = lo;
                *(float2*)&sS[(row+8)*FSP + col] = hi;
            }
        }
        __syncthreads();

        // ---- softmax (scalar fp32) ----
        const bool diag = (jb >= 2*qb);
        const int col0 = jb * 64;
#pragma unroll
        for (int rr = 0; rr < 8; rr++) {
            int row = warp*8 + rr;
            int grow = grow0 + row;
            float s1 = sS[row*FSP + lane];
            float s2 = sS[row*FSP + 32 + lane];
            if (diag) {
                if (col0 + lane > grow)      s1 = -1e30f;
                if (col0 + 32 + lane > grow) s2 = -1e30f;
            }
            float mx = fmaxf(s1, s2);
#pragma unroll
            for (int o = 16; o > 0; o >>= 1)
                mx = fmaxf(mx, __shfl_xor_sync(0xffffffffu, mx, o));
            float m_new = fmaxf(m_r[rr], mx);
            float corr = __expf(m_r[rr] - m_new);
            float p1 = __expf(s1 - m_new);
            float p2 = __expf(s2 - m_new);
            float ps = p1 + p2;
#pragma unroll
            for (int o = 16; o > 0; o >>= 1)
                ps += __shfl_xor_sync(0xffffffffu, ps, o);
            l_r[rr] = l_r[rr] * corr + ps;
            m_r[rr] = m_new;
            sS[row*FSP + lane]      = tf32_round(p1);
            sS[row*FSP + 32 + lane] = tf32_round(p2);
            if (lane == 0) scorr[row] = corr;
        }
        __syncthreads();

        // ---- PV: warp tile 32x32, 8 ks steps ----
        float cr0[2], cr1[2];
#pragma unroll
        for (int i = 0; i < 2; i++) {
            const int row = wm*32 + i*16 + qd;
            cr0[i] = scorr[row];
            cr1[i] = scorr[row+8];
        }
#pragma unroll
        for (int i = 0; i < 2; i++)
#pragma unroll
            for (int j = 0; j < 4; j++) {
                oacc[i][j][0] *= cr0[i]; oacc[i][j][1] *= cr0[i];
                oacc[i][j][2] *= cr1[i]; oacc[i][j][3] *= cr1[i];
            }

        const uint32_t aS0 = smb + (uint32_t)((FSS + (wm*32)*FSP)*4) + lmS;
        const uint32_t bV0 = smb + (uint32_t)((FSV + (wn*32)*FVP)*4) + lmS;
#pragma unroll
        for (int ks = 0; ks < 8; ks++) {
            const uint32_t kk4 = (uint32_t)(ks*32);
            uint32_t pa[2][4], vb[4][2];
            LDSM4(pa[0][0], pa[0][1], pa[0][2], pa[0][3], aS0 + kk4);
            LDSM4(pa[1][0], pa[1][1], pa[1][2], pa[1][3], aS0 + (uint32_t)(16*FSP*4) + kk4);
            LDSM4(vb[0][0], vb[1][0], vb[0][1], vb[1][1], bV0 + kk4);
            LDSM4(vb[2][0], vb[3][0], vb[2][1], vb[3][1], bV0 + (uint32_t)(16*FVP*4) + kk4);
#pragma unroll
            for (int i = 0; i < 2; i++)
#pragma unroll
                for (int j = 0; j < 4; j++)
                    mma_tf32(oacc[i][j], pa[i], vb[j]);
        }
    }

    __syncthreads();
#pragma unroll
    for (int rr = 0; rr < 8; rr++)
        if (lane == 0) scorr[warp*8 + rr] = 1.f / l_r[rr];
    __syncthreads();

#pragma unroll
    for (int i = 0; i < 2; i++) {
        const int row = wm*32 + i*16 + qd;
        const float inv0 = scorr[row], inv1 = scorr[row+8];
        float* d0 = ctx + ((size_t)(b*SEQ + grow0 + row  ) * NH + h) * HD;
        float* d1 = ctx + ((size_t)(b*SEQ + grow0 + row+8) * NH + h) * HD;
#pragma unroll
        for (int j = 0; j < 4; j++) {
            const int col = wn*32 + j*8 + 2*r4;
            float2 lo, hi;
            lo.x = tf32_round(oacc[i][j][0]*inv0);
            lo.y = tf32_round(oacc[i][j][1]*inv0);
            hi.x = tf32_round(oacc[i][j][2]*inv1);
            hi.y = tf32_round(oacc[i][j][3]*inv1);
            *(float2*)(d0 + col) = lo;
            *(float2*)(d1 + col) = hi;
        }
    }
}

// ---------------------------------------------------------------------------
extern "C" void kernel_launch(void* const* d_in, const int* in_sizes, int n_in,
                              void* d_out, int out_size)
{
    const float* hs   = (const float*)d_in[0];
    const float* cosp = (const float*)d_in[1];
    const float* sinp = (const float*)d_in[2];
    const float* Wq   = (const float*)d_in[3];
    const float* Wk   = (const float*)d_in[4];
    const float* Wv   = (const float*)d_in[5];
    const float* Wo   = (const float*)d_in[6];
    float* out = (float*)d_out;

    float *qkv, *ctx, *hs_t, *wqkv, *wo;
    cudaGetSymbolAddress((void**)&qkv,  g_qkv);
    cudaGetSymbolAddress((void**)&ctx,  g_ctx);
    cudaGetSymbolAddress((void**)&hs_t, g_hs);
    cudaGetSymbolAddress((void**)&wqkv, g_wqkv);
    cudaGetSymbolAddress((void**)&wo,   g_wo);

    cudaFuncSetAttribute(gemm_mma, cudaFuncAttributeMaxDynamicSharedMemorySize,
                         (int)GEMM_SMEM);
    cudaFuncSetAttribute(flash_mma_kernel, cudaFuncAttributeMaxDynamicSharedMemorySize,
                         (int)FLASH_SMEM);

    const int M = MTOT;  // 4096

    // 1) fused tf32 pre-rounding of all inputs
    round5_kernel<<<(N4_TOT + 255)/256, 256>>>(hs, Wq, Wk, Wv, Wo,
                                               hs_t, wqkv, wo);

    // 2) fused QKV projection (CTA 128x256, 512 threads)
    gemm_mma<<<dim3(QKVW/256, M/128), 512, GEMM_SMEM>>>(hs_t, wqkv, qkv,
                                                        M, QKVW, HIDDEN);

    // 3) fused RoPE + rounding of q/k/v
    rope_round_kernel<<<(ROPE_TOT + 255)/256, 256>>>(qkv, cosp, sinp);

    // 4) attention
    flash_mma_kernel<<<dim3(SEQ/128, NH, BATCH), 512, FLASH_SMEM>>>(qkv, ctx);

    // 5) output projection
    gemm_mma<<<dim3(HIDDEN/256, M/128), 512, GEMM_SMEM>>>(ctx, wo, out,
                                                          M, HIDDEN, HIDDEN);
}